// round 3
// baseline (speedup 1.0000x reference)
#include <cuda_runtime.h>
#include <cuda_fp16.h>
#include <cstdint>

#define BS   8
#define SEQ  2048
#define DIM  512
#define MQ   128
#define NK   64
#define DV   256
#define NQT  (SEQ/MQ)   // 16
#define NKT  (SEQ/NK)   // 32

__device__ __half g_Qh[(size_t)BS*SEQ*DIM];
__device__ __half g_Kh[(size_t)BS*SEQ*DIM];
__device__ __half g_Vh[(size_t)BS*SEQ*DIM];

#define SM_Q 0
#define SM_K 131072
#define SM_V (131072 + 65536)
#define SM_TOTAL (SM_V + 32768)   // 229376 bytes

__device__ __forceinline__ uint32_t smem_u32(const void* p) {
    uint32_t a;
    asm("{ .reg .u64 t; cvta.to.shared.u64 t, %1; cvt.u32.u64 %0, t; }" : "=r"(a) : "l"(p));
    return a;
}
// K-major SW128 blocked atoms: atom = 8 rows x 64 halfs (1024B).
// atom index = (col/64)*natomrows + row/8 ; swizzle XOR within atom.
__device__ __forceinline__ uint32_t km_off(int row, int col, int natomrows) {
    uint32_t off = ((uint32_t)((col >> 6) * natomrows + (row >> 3)) << 10)
                 + ((uint32_t)(row & 7) << 7) + ((uint32_t)(col & 63) << 1);
    return off ^ ((off >> 3) & 0x70u);
}
__device__ __forceinline__ float ex2f(float x) {
    float y;
    asm("ex2.approx.f32 %0, %1;" : "=f"(y) : "f"(x));
    return y;
}
__device__ __forceinline__ void cp16(uint32_t dst, const void* src) {
    asm volatile("cp.async.cg.shared.global [%0], [%1], 16;" :: "r"(dst), "l"(src));
}
#define CP_COMMIT() asm volatile("cp.async.commit_group;" ::: "memory")
#define CP_WAIT0()  asm volatile("cp.async.wait_group 0;" ::: "memory")

__device__ __forceinline__ void ldsm_x4(uint32_t* r, uint32_t addr) {
    asm volatile("ldmatrix.sync.aligned.m8n8.x4.shared.b16 {%0,%1,%2,%3}, [%4];"
        : "=r"(r[0]), "=r"(r[1]), "=r"(r[2]), "=r"(r[3]) : "r"(addr));
}
__device__ __forceinline__ void ldsm_x4t(uint32_t* r, uint32_t addr) {
    asm volatile("ldmatrix.sync.aligned.m8n8.x4.trans.shared.b16 {%0,%1,%2,%3}, [%4];"
        : "=r"(r[0]), "=r"(r[1]), "=r"(r[2]), "=r"(r[3]) : "r"(addr));
}
__device__ __forceinline__ void mma16816(float* c, const uint32_t* a, const uint32_t* b) {
    asm volatile("mma.sync.aligned.m16n8k16.row.col.f32.f16.f16.f32 "
        "{%0,%1,%2,%3}, {%4,%5,%6,%7}, {%8,%9}, {%0,%1,%2,%3};"
        : "+f"(c[0]), "+f"(c[1]), "+f"(c[2]), "+f"(c[3])
        : "r"(a[0]), "r"(a[1]), "r"(a[2]), "r"(a[3]), "r"(b[0]), "r"(b[1]));
}

// fp32 -> f16 conversion pre-pass for Q, K, V
__global__ void convert_kernel(const float* __restrict__ q, const float* __restrict__ k,
                               const float* __restrict__ v, int n4) {
    int i = blockIdx.x * blockDim.x + threadIdx.x;
    if (i >= n4) return;
    float4 a = reinterpret_cast<const float4*>(q)[i];
    float4 b = reinterpret_cast<const float4*>(k)[i];
    float4 c = reinterpret_cast<const float4*>(v)[i];
    __half2 h;
    uint2 u;
    h = __floats2half2_rn(a.x, a.y); u.x = *reinterpret_cast<uint32_t*>(&h);
    h = __floats2half2_rn(a.z, a.w); u.y = *reinterpret_cast<uint32_t*>(&h);
    reinterpret_cast<uint2*>(g_Qh)[i] = u;
    h = __floats2half2_rn(b.x, b.y); u.x = *reinterpret_cast<uint32_t*>(&h);
    h = __floats2half2_rn(b.z, b.w); u.y = *reinterpret_cast<uint32_t*>(&h);
    reinterpret_cast<uint2*>(g_Kh)[i] = u;
    h = __floats2half2_rn(c.x, c.y); u.x = *reinterpret_cast<uint32_t*>(&h);
    h = __floats2half2_rn(c.z, c.w); u.y = *reinterpret_cast<uint32_t*>(&h);
    reinterpret_cast<uint2*>(g_Vh)[i] = u;
}

// FlashAttention-2, mma.sync.m16n8k16, 8 warps m-split.
// grid (NQT, BS, 2), block 256. Each CTA: q rows [q0, q0+128), d cols [dofs, dofs+256).
__global__ void __launch_bounds__(256, 1)
attn_kernel(const int* __restrict__ um_p, const int* __restrict__ cd_p,
            float* __restrict__ out) {
    extern __shared__ char smem[];
    const uint32_t sb = smem_u32(smem);
    const int tid = threadIdx.x, lane = tid & 31, w = tid >> 5;
    const int qi = blockIdx.x, b = blockIdx.y, ds = blockIdx.z;
    const int q0 = qi * MQ, dofs = ds * DV;
    const int um = um_p[0];
    const float cl2 = 1.4426950408889634f * rsqrtf((float)cd_p[0]);
    const int nkt = um ? (2 * qi + 2) : NKT;
    const float NEG = __int_as_float(0xff800000);

    // Q tile -> smem (async; waited together with first K/V)
    {
        const __half* Qg = g_Qh + ((size_t)(b * SEQ + q0)) * DIM;
        #pragma unroll 4
        for (int i = tid; i < MQ * (DIM / 8); i += 256) {
            int r = i >> 6, c8 = i & 63;
            cp16(sb + SM_Q + km_off(r, c8 * 8, 16), Qg + (size_t)r * DIM + c8 * 8);
        }
        CP_COMMIT();
    }

    float o[32][4];
    #pragma unroll
    for (int j = 0; j < 32; j++) { o[j][0] = 0.f; o[j][1] = 0.f; o[j][2] = 0.f; o[j][3] = 0.f; }
    float m0 = NEG, m1 = NEG, l0 = 0.f, l1 = 0.f;

    const int qrow0 = q0 + w * 16 + (lane >> 2);
    const int qrow1 = qrow0 + 8;

    for (int kt = 0; kt < nkt; kt++) {
        const int k0 = kt * NK;
        // ---- stage K/V tiles ----
        __syncthreads();                       // prior readers of SM_K/SM_V done
        {
            const __half* Kg = g_Kh + ((size_t)(b * SEQ + k0)) * DIM;
            const __half* Vg = g_Vh + ((size_t)(b * SEQ + k0)) * DIM + dofs;
            #pragma unroll 4
            for (int i = tid; i < NK * (DIM / 8); i += 256) {
                int r = i >> 6, c8 = i & 63;
                cp16(sb + SM_K + km_off(r, c8 * 8, 8), Kg + (size_t)r * DIM + c8 * 8);
            }
            #pragma unroll 2
            for (int i = tid; i < NK * (DV / 8); i += 256) {
                int r = i >> 5, c8 = i & 31;
                cp16(sb + SM_V + km_off(r, c8 * 8, 8), Vg + (size_t)r * DIM + c8 * 8);
            }
            CP_COMMIT();
            CP_WAIT0();
        }
        __syncthreads();

        // ---- S = Q K^T : s[nt][4], nt over 8 key-tiles of 8 ----
        float s[8][4];
        #pragma unroll
        for (int nt = 0; nt < 8; nt++) { s[nt][0] = 0.f; s[nt][1] = 0.f; s[nt][2] = 0.f; s[nt][3] = 0.f; }

        const int arow = w * 16 + (lane & 15);
        const int acol = (lane >> 4) << 3;
        const int brow = lane & 7;
        const int bcol = ((lane >> 3) & 3) << 3;
        #pragma unroll 4
        for (int kc2 = 0; kc2 < 16; kc2++) {
            uint32_t a0[4], a1[4];
            ldsm_x4(a0, sb + SM_Q + km_off(arow, kc2 * 32 + acol, 16));
            ldsm_x4(a1, sb + SM_Q + km_off(arow, kc2 * 32 + 16 + acol, 16));
            #pragma unroll
            for (int nt = 0; nt < 8; nt++) {
                uint32_t bb[4];
                ldsm_x4(bb, sb + SM_K + km_off(nt * 8 + brow, kc2 * 32 + bcol, 8));
                mma16816(s[nt], a0, bb);
                mma16816(s[nt], a1, bb + 2);
            }
        }

        // ---- causal mask (only diagonal-overlapping iterations) ----
        if (um && kt >= 2 * qi) {
            #pragma unroll
            for (int nt = 0; nt < 8; nt++) {
                int c = k0 + nt * 8 + ((lane & 3) << 1);
                if (c     > qrow0) s[nt][0] = NEG;
                if (c + 1 > qrow0) s[nt][1] = NEG;
                if (c     > qrow1) s[nt][2] = NEG;
                if (c + 1 > qrow1) s[nt][3] = NEG;
            }
        }

        // ---- online softmax ----
        float vx0 = NEG, vx1 = NEG;
        #pragma unroll
        for (int nt = 0; nt < 8; nt++) {
            vx0 = fmaxf(vx0, fmaxf(s[nt][0], s[nt][1]));
            vx1 = fmaxf(vx1, fmaxf(s[nt][2], s[nt][3]));
        }
        vx0 = fmaxf(vx0, __shfl_xor_sync(0xffffffffu, vx0, 1));
        vx0 = fmaxf(vx0, __shfl_xor_sync(0xffffffffu, vx0, 2));
        vx1 = fmaxf(vx1, __shfl_xor_sync(0xffffffffu, vx1, 1));
        vx1 = fmaxf(vx1, __shfl_xor_sync(0xffffffffu, vx1, 2));
        const float nm0 = fmaxf(m0, vx0), nm1 = fmaxf(m1, vx1);
        const float al0 = ex2f((m0 - nm0) * cl2), al1 = ex2f((m1 - nm1) * cl2);

        float sum0 = 0.f, sum1 = 0.f;
        #pragma unroll
        for (int nt = 0; nt < 8; nt++) {
            s[nt][0] = ex2f((s[nt][0] - nm0) * cl2);
            s[nt][1] = ex2f((s[nt][1] - nm0) * cl2);
            s[nt][2] = ex2f((s[nt][2] - nm1) * cl2);
            s[nt][3] = ex2f((s[nt][3] - nm1) * cl2);
            sum0 += s[nt][0] + s[nt][1];
            sum1 += s[nt][2] + s[nt][3];
        }
        sum0 += __shfl_xor_sync(0xffffffffu, sum0, 1);
        sum0 += __shfl_xor_sync(0xffffffffu, sum0, 2);
        sum1 += __shfl_xor_sync(0xffffffffu, sum1, 1);
        sum1 += __shfl_xor_sync(0xffffffffu, sum1, 2);
        l0 = l0 * al0 + sum0;
        l1 = l1 * al1 + sum1;
        m0 = nm0; m1 = nm1;

        #pragma unroll
        for (int j = 0; j < 32; j++) {
            o[j][0] *= al0; o[j][1] *= al0; o[j][2] *= al1; o[j][3] *= al1;
        }

        // ---- P (f16) as A-fragments, straight from registers ----
        uint32_t pa[4][4];
        #pragma unroll
        for (int kc = 0; kc < 4; kc++) {
            __half2 h;
            h = __floats2half2_rn(s[2*kc][0],   s[2*kc][1]);   pa[kc][0] = *reinterpret_cast<uint32_t*>(&h);
            h = __floats2half2_rn(s[2*kc][2],   s[2*kc][3]);   pa[kc][1] = *reinterpret_cast<uint32_t*>(&h);
            h = __floats2half2_rn(s[2*kc+1][0], s[2*kc+1][1]); pa[kc][2] = *reinterpret_cast<uint32_t*>(&h);
            h = __floats2half2_rn(s[2*kc+1][2], s[2*kc+1][3]); pa[kc][3] = *reinterpret_cast<uint32_t*>(&h);
        }

        // ---- O += P V ----
        const int vrow = lane & 15;
        const int vcol = (lane >> 4) << 3;
        #pragma unroll 4
        for (int dt2 = 0; dt2 < 16; dt2++) {
            #pragma unroll
            for (int kc = 0; kc < 4; kc++) {
                uint32_t bb[4];
                ldsm_x4t(bb, sb + SM_V + km_off(kc * 16 + vrow, dt2 * 16 + vcol, 8));
                mma16816(o[2*dt2],     pa[kc], bb);
                mma16816(o[2*dt2 + 1], pa[kc], bb + 2);
            }
        }
    }

    // ---- epilogue: O / l -> gmem (float2 stores) ----
    const float i0 = 1.f / l0, i1 = 1.f / l1;
    float* out0 = out + ((size_t)b * SEQ + qrow0) * DIM + dofs;
    float* out1 = out + ((size_t)b * SEQ + qrow1) * DIM + dofs;
    const int cofs = (lane & 3) << 1;
    #pragma unroll
    for (int j = 0; j < 32; j++) {
        float2 v0 = make_float2(o[j][0] * i0, o[j][1] * i0);
        float2 v1 = make_float2(o[j][2] * i1, o[j][3] * i1);
        *reinterpret_cast<float2*>(out0 + j * 8 + cofs) = v0;
        *reinterpret_cast<float2*>(out1 + j * 8 + cofs) = v1;
    }
}

extern "C" void kernel_launch(void* const* d_in, const int* in_sizes, int n_in,
                              void* d_out, int out_size) {
    const float* Q = (const float*)d_in[0];
    const float* K = (const float*)d_in[1];
    const float* V = (const float*)d_in[2];
    const int* use_mask = (const int*)d_in[3];
    const int* cell_dim = (const int*)d_in[4];
    float* out = (float*)d_out;

    int n4 = (BS * SEQ * DIM) / 4;
    convert_kernel<<<(n4 + 255) / 256, 256>>>(Q, K, V, n4);

    cudaFuncSetAttribute(attn_kernel, cudaFuncAttributeMaxDynamicSharedMemorySize, SM_TOTAL);
    attn_kernel<<<dim3(NQT, BS, 2), 256, SM_TOTAL>>>(use_mask, cell_dim, out);
}

// round 4
// speedup vs baseline: 1.6522x; 1.6522x over previous
#include <cuda_runtime.h>
#include <cuda_fp16.h>
#include <cstdint>

#define BS   8
#define SEQ  2048
#define DIM  512
#define MQ   128
#define NK   32
#define DV   256
#define NQT  (SEQ/MQ)   // 16
#define NKT  (SEQ/NK)   // 64

__device__ __half g_Qh[(size_t)BS*SEQ*DIM];
__device__ __half g_Kh[(size_t)BS*SEQ*DIM];
__device__ __half g_Vh[(size_t)BS*SEQ*DIM];

#define SM_Q   0
#define SM_K   131072
#define SM_V   (131072 + 65536)
#define KBUF   32768
#define VBUF   16384
#define SM_TOTAL (SM_V + 2*VBUF)   // 229376 bytes

__device__ __forceinline__ uint32_t smem_u32(const void* p) {
    uint32_t a;
    asm("{ .reg .u64 t; cvta.to.shared.u64 t, %1; cvt.u32.u64 %0, t; }" : "=r"(a) : "l"(p));
    return a;
}
// K-major SW128 blocked atoms: atom = 8 rows x 64 halfs (1024B).
__device__ __forceinline__ uint32_t km_off(int row, int col, int natomrows) {
    uint32_t off = ((uint32_t)((col >> 6) * natomrows + (row >> 3)) << 10)
                 + ((uint32_t)(row & 7) << 7) + ((uint32_t)(col & 63) << 1);
    return off ^ ((off >> 3) & 0x70u);
}
__device__ __forceinline__ float ex2f(float x) {
    float y;
    asm("ex2.approx.f32 %0, %1;" : "=f"(y) : "f"(x));
    return y;
}
__device__ __forceinline__ void cp16(uint32_t dst, const void* src) {
    asm volatile("cp.async.cg.shared.global [%0], [%1], 16;" :: "r"(dst), "l"(src));
}
#define CP_COMMIT() asm volatile("cp.async.commit_group;" ::: "memory")
#define CP_WAIT1()  asm volatile("cp.async.wait_group 1;" ::: "memory")

__device__ __forceinline__ void ldsm_x4(uint32_t* r, uint32_t addr) {
    asm volatile("ldmatrix.sync.aligned.m8n8.x4.shared.b16 {%0,%1,%2,%3}, [%4];"
        : "=r"(r[0]), "=r"(r[1]), "=r"(r[2]), "=r"(r[3]) : "r"(addr));
}
__device__ __forceinline__ void ldsm_x4t(uint32_t* r, uint32_t addr) {
    asm volatile("ldmatrix.sync.aligned.m8n8.x4.trans.shared.b16 {%0,%1,%2,%3}, [%4];"
        : "=r"(r[0]), "=r"(r[1]), "=r"(r[2]), "=r"(r[3]) : "r"(addr));
}
__device__ __forceinline__ void mma16816(float* c, const uint32_t* a, const uint32_t* b) {
    asm volatile("mma.sync.aligned.m16n8k16.row.col.f32.f16.f16.f32 "
        "{%0,%1,%2,%3}, {%4,%5,%6,%7}, {%8,%9}, {%0,%1,%2,%3};"
        : "+f"(c[0]), "+f"(c[1]), "+f"(c[2]), "+f"(c[3])
        : "r"(a[0]), "r"(a[1]), "r"(a[2]), "r"(a[3]), "r"(b[0]), "r"(b[1]));
}

__global__ void convert_kernel(const float* __restrict__ q, const float* __restrict__ k,
                               const float* __restrict__ v, int n4) {
    int i = blockIdx.x * blockDim.x + threadIdx.x;
    if (i >= n4) return;
    float4 a = reinterpret_cast<const float4*>(q)[i];
    float4 b = reinterpret_cast<const float4*>(k)[i];
    float4 c = reinterpret_cast<const float4*>(v)[i];
    __half2 h;
    uint2 u;
    h = __floats2half2_rn(a.x, a.y); u.x = *reinterpret_cast<uint32_t*>(&h);
    h = __floats2half2_rn(a.z, a.w); u.y = *reinterpret_cast<uint32_t*>(&h);
    reinterpret_cast<uint2*>(g_Qh)[i] = u;
    h = __floats2half2_rn(b.x, b.y); u.x = *reinterpret_cast<uint32_t*>(&h);
    h = __floats2half2_rn(b.z, b.w); u.y = *reinterpret_cast<uint32_t*>(&h);
    reinterpret_cast<uint2*>(g_Kh)[i] = u;
    h = __floats2half2_rn(c.x, c.y); u.x = *reinterpret_cast<uint32_t*>(&h);
    h = __floats2half2_rn(c.z, c.w); u.y = *reinterpret_cast<uint32_t*>(&h);
    reinterpret_cast<uint2*>(g_Vh)[i] = u;
}

// Issue cp.async for one K/V tile (32 keys) into the given buffers.
__device__ __forceinline__ void load_kv(const __half* Kg, const __half* Vg, int tid,
                                        uint32_t kbuf, uint32_t vbuf) {
    #pragma unroll
    for (int i = tid; i < NK * (DIM / 8); i += 256) {   // 8 per thread
        int r = i >> 6, c8 = i & 63;
        cp16(kbuf + km_off(r, c8 * 8, NK / 8), Kg + (size_t)r * DIM + c8 * 8);
    }
    #pragma unroll
    for (int i = tid; i < NK * (DV / 8); i += 256) {    // 4 per thread
        int r = i >> 5, c8 = i & 31;
        cp16(vbuf + km_off(r, c8 * 8, NK / 8), Vg + (size_t)r * DIM + c8 * 8);
    }
}

// FlashAttention-2, mma.sync.m16n8k16, 8 warps m-split, double-buffered K/V.
// grid (NQT, BS, 2), block 256. qi remapped heavy-first.
__global__ void __launch_bounds__(256, 1)
attn_kernel(const int* __restrict__ um_p, const int* __restrict__ cd_p,
            float* __restrict__ out) {
    extern __shared__ char smem[];
    const uint32_t sb = smem_u32(smem);
    const int tid = threadIdx.x, lane = tid & 31, w = tid >> 5;
    const int qi = (NQT - 1) - blockIdx.x;       // heavy tiles first
    const int b = blockIdx.y, ds = blockIdx.z;
    const int q0 = qi * MQ, dofs = ds * DV;
    const int um = um_p[0];
    const float cl2 = 1.4426950408889634f * rsqrtf((float)cd_p[0]);
    const int nkt = um ? (4 * qi + 4) : NKT;
    const float NEG = __int_as_float(0xff800000);

    const __half* Kg0 = g_Kh + ((size_t)(b * SEQ)) * DIM;
    const __half* Vg0 = g_Vh + ((size_t)(b * SEQ)) * DIM + dofs;

    // ---- prologue: async Q, then tiles 0 and 1 ----
    {
        const __half* Qg = g_Qh + ((size_t)(b * SEQ + q0)) * DIM;
        #pragma unroll 8
        for (int i = tid; i < MQ * (DIM / 8); i += 256) {
            int r = i >> 6, c8 = i & 63;
            cp16(sb + SM_Q + km_off(r, c8 * 8, 16), Qg + (size_t)r * DIM + c8 * 8);
        }
        CP_COMMIT();
    }
    load_kv(Kg0, Vg0, tid, sb + SM_K, sb + SM_V);
    CP_COMMIT();
    load_kv(Kg0 + (size_t)NK * DIM, Vg0 + (size_t)NK * DIM, tid,
            sb + SM_K + KBUF, sb + SM_V + VBUF);
    CP_COMMIT();

    float o[32][4];
    #pragma unroll
    for (int j = 0; j < 32; j++) { o[j][0] = 0.f; o[j][1] = 0.f; o[j][2] = 0.f; o[j][3] = 0.f; }
    float m0 = NEG, m1 = NEG, l0 = 0.f, l1 = 0.f;

    const int qrow0 = q0 + w * 16 + (lane >> 2);
    const int qrow1 = qrow0 + 8;
    const int arow = w * 16 + (lane & 15);
    const int acol = (lane >> 4) << 3;
    const int brow = lane & 7;
    const int bcol = ((lane >> 3) & 3) << 3;
    const int vrow = lane & 15;
    const int vcol = (lane >> 4) << 3;

    for (int kt = 0; kt < nkt; kt++) {
        const int k0 = kt * NK;
        const uint32_t kb = sb + SM_K + (kt & 1) * KBUF;
        const uint32_t vb = sb + SM_V + (kt & 1) * VBUF;

        CP_WAIT1();              // tile kt landed (tile kt+1 may be in flight)
        __syncthreads();

        // ---- S = Q K^T ----
        float s[4][4];
        #pragma unroll
        for (int nt = 0; nt < 4; nt++) { s[nt][0] = 0.f; s[nt][1] = 0.f; s[nt][2] = 0.f; s[nt][3] = 0.f; }
        #pragma unroll
        for (int kc2 = 0; kc2 < 16; kc2++) {
            uint32_t a0[4], a1[4];
            ldsm_x4(a0, sb + SM_Q + km_off(arow, kc2 * 32 + acol, 16));
            ldsm_x4(a1, sb + SM_Q + km_off(arow, kc2 * 32 + 16 + acol, 16));
            #pragma unroll
            for (int nt = 0; nt < 4; nt++) {
                uint32_t bb[4];
                ldsm_x4(bb, kb + km_off(nt * 8 + brow, kc2 * 32 + bcol, NK / 8));
                mma16816(s[nt], a0, bb);
                mma16816(s[nt], a1, bb + 2);
            }
        }

        // ---- causal mask (diagonal tiles only) ----
        if (um && kt >= 4 * qi) {
            #pragma unroll
            for (int nt = 0; nt < 4; nt++) {
                int c = k0 + nt * 8 + ((lane & 3) << 1);
                if (c     > qrow0) s[nt][0] = NEG;
                if (c + 1 > qrow0) s[nt][1] = NEG;
                if (c     > qrow1) s[nt][2] = NEG;
                if (c + 1 > qrow1) s[nt][3] = NEG;
            }
        }

        // ---- online softmax ----
        float vx0 = NEG, vx1 = NEG;
        #pragma unroll
        for (int nt = 0; nt < 4; nt++) {
            vx0 = fmaxf(vx0, fmaxf(s[nt][0], s[nt][1]));
            vx1 = fmaxf(vx1, fmaxf(s[nt][2], s[nt][3]));
        }
        vx0 = fmaxf(vx0, __shfl_xor_sync(0xffffffffu, vx0, 1));
        vx0 = fmaxf(vx0, __shfl_xor_sync(0xffffffffu, vx0, 2));
        vx1 = fmaxf(vx1, __shfl_xor_sync(0xffffffffu, vx1, 1));
        vx1 = fmaxf(vx1, __shfl_xor_sync(0xffffffffu, vx1, 2));
        const float nm0 = fmaxf(m0, vx0), nm1 = fmaxf(m1, vx1);

        float sum0 = 0.f, sum1 = 0.f;
        #pragma unroll
        for (int nt = 0; nt < 4; nt++) {
            s[nt][0] = ex2f((s[nt][0] - nm0) * cl2);
            s[nt][1] = ex2f((s[nt][1] - nm0) * cl2);
            s[nt][2] = ex2f((s[nt][2] - nm1) * cl2);
            s[nt][3] = ex2f((s[nt][3] - nm1) * cl2);
            sum0 += s[nt][0] + s[nt][1];
            sum1 += s[nt][2] + s[nt][3];
        }
        sum0 += __shfl_xor_sync(0xffffffffu, sum0, 1);
        sum0 += __shfl_xor_sync(0xffffffffu, sum0, 2);
        sum1 += __shfl_xor_sync(0xffffffffu, sum1, 1);
        sum1 += __shfl_xor_sync(0xffffffffu, sum1, 2);

        const bool rescale = (vx0 > m0) || (vx1 > m1);
        const float al0 = ex2f((m0 - nm0) * cl2), al1 = ex2f((m1 - nm1) * cl2);
        l0 = l0 * al0 + sum0;
        l1 = l1 * al1 + sum1;
        m0 = nm0; m1 = nm1;
        if (__any_sync(0xffffffffu, rescale)) {
            #pragma unroll
            for (int j = 0; j < 32; j++) {
                o[j][0] *= al0; o[j][1] *= al0; o[j][2] *= al1; o[j][3] *= al1;
            }
        }

        // ---- P (f16) A-fragments directly from registers ----
        uint32_t pa[2][4];
        #pragma unroll
        for (int kc = 0; kc < 2; kc++) {
            __half2 h;
            h = __floats2half2_rn(s[2*kc][0],   s[2*kc][1]);   pa[kc][0] = *reinterpret_cast<uint32_t*>(&h);
            h = __floats2half2_rn(s[2*kc][2],   s[2*kc][3]);   pa[kc][1] = *reinterpret_cast<uint32_t*>(&h);
            h = __floats2half2_rn(s[2*kc+1][0], s[2*kc+1][1]); pa[kc][2] = *reinterpret_cast<uint32_t*>(&h);
            h = __floats2half2_rn(s[2*kc+1][2], s[2*kc+1][3]); pa[kc][3] = *reinterpret_cast<uint32_t*>(&h);
        }

        // ---- O += P V ----
        #pragma unroll
        for (int dt2 = 0; dt2 < 16; dt2++) {
            #pragma unroll
            for (int kc = 0; kc < 2; kc++) {
                uint32_t bb[4];
                ldsm_x4t(bb, vb + km_off(kc * 16 + vrow, dt2 * 16 + vcol, NK / 8));
                mma16816(o[2*dt2],     pa[kc], bb);
                mma16816(o[2*dt2 + 1], pa[kc], bb + 2);
            }
        }

        // ---- prefetch tile kt+2 into the buffer just consumed ----
        __syncthreads();
        if (kt + 2 < nkt) {
            load_kv(Kg0 + (size_t)(k0 + 2 * NK) * DIM, Vg0 + (size_t)(k0 + 2 * NK) * DIM,
                    tid, kb, vb);
        }
        CP_COMMIT();             // commit every iter (possibly empty) to keep group counts aligned
    }

    // ---- epilogue ----
    const float i0 = 1.f / l0, i1 = 1.f / l1;
    float* out0 = out + ((size_t)b * SEQ + qrow0) * DIM + dofs;
    float* out1 = out + ((size_t)b * SEQ + qrow1) * DIM + dofs;
    const int cofs = (lane & 3) << 1;
    #pragma unroll
    for (int j = 0; j < 32; j++) {
        float2 v0 = make_float2(o[j][0] * i0, o[j][1] * i0);
        float2 v1 = make_float2(o[j][2] * i1, o[j][3] * i1);
        *reinterpret_cast<float2*>(out0 + j * 8 + cofs) = v0;
        *reinterpret_cast<float2*>(out1 + j * 8 + cofs) = v1;
    }
}

extern "C" void kernel_launch(void* const* d_in, const int* in_sizes, int n_in,
                              void* d_out, int out_size) {
    const float* Q = (const float*)d_in[0];
    const float* K = (const float*)d_in[1];
    const float* V = (const float*)d_in[2];
    const int* use_mask = (const int*)d_in[3];
    const int* cell_dim = (const int*)d_in[4];
    float* out = (float*)d_out;

    int n4 = (BS * SEQ * DIM) / 4;
    convert_kernel<<<(n4 + 255) / 256, 256>>>(Q, K, V, n4);

    cudaFuncSetAttribute(attn_kernel, cudaFuncAttributeMaxDynamicSharedMemorySize, SM_TOTAL);
    attn_kernel<<<dim3(NQT, BS, 2), 256, SM_TOTAL>>>(use_mask, cell_dim, out);
}